// round 1
// baseline (speedup 1.0000x reference)
#include <cuda_runtime.h>
#include <math.h>

#define BATCH 2
#define SEQ   2048
#define DMODEL 1024
#define NHEADS 16
#define HDIM  64
#define MROWS (BATCH*SEQ)   // 4096

// Scratch (allocation-free rule: device globals)
__device__ float g_Q[(size_t)MROWS * DMODEL];
__device__ float g_K[(size_t)MROWS * DMODEL];
__device__ float g_V[(size_t)MROWS * DMODEL];
__device__ float g_AO[(size_t)MROWS * DMODEL];

// ---------------------------------------------------------------------------
// SGEMM: C[M,N] = A[M,K] @ B[K,N] + bias[N]
// 128x128 block tile, BK=8, 256 threads, 8x8 per thread (split 4+4 halves)
// ---------------------------------------------------------------------------
__global__ __launch_bounds__(256) void sgemm_bias(
    const float* __restrict__ A, const float* __restrict__ B,
    const float* __restrict__ bias, float* __restrict__ C,
    int M, int N, int K)
{
    __shared__ float As[8][128];
    __shared__ float Bs[8][128];

    const int tid  = threadIdx.x;
    const int brow = blockIdx.y * 128;
    const int bcol = blockIdx.x * 128;
    const int tx = tid & 15;
    const int ty = tid >> 4;

    // A tile load mapping: 128 rows x 8 cols, one float4 per thread
    const int arow = tid >> 1;           // 0..127
    const int akg  = (tid & 1) * 4;      // 0 or 4
    // B tile load mapping: 8 rows x 128 cols, one float4 per thread
    const int bkr  = tid >> 5;           // 0..7
    const int bkc  = (tid & 31) * 4;     // 0..124

    const float* Ap = A + (size_t)(brow + arow) * K + akg;
    const float* Bp = B + (size_t)bkr * N + bcol + bkc;

    float acc[8][8];
    #pragma unroll
    for (int i = 0; i < 8; i++)
        #pragma unroll
        for (int j = 0; j < 8; j++) acc[i][j] = 0.f;

    for (int k0 = 0; k0 < K; k0 += 8) {
        float4 a4 = *(const float4*)(Ap + k0);
        float4 b4 = *(const float4*)(Bp + (size_t)k0 * N);
        As[akg + 0][arow] = a4.x;
        As[akg + 1][arow] = a4.y;
        As[akg + 2][arow] = a4.z;
        As[akg + 3][arow] = a4.w;
        *(float4*)&Bs[bkr][bkc] = b4;
        __syncthreads();

        #pragma unroll
        for (int kk = 0; kk < 8; kk++) {
            float ar[8], br[8];
            *(float4*)&ar[0] = *(const float4*)&As[kk][ty * 4];
            *(float4*)&ar[4] = *(const float4*)&As[kk][64 + ty * 4];
            *(float4*)&br[0] = *(const float4*)&Bs[kk][tx * 4];
            *(float4*)&br[4] = *(const float4*)&Bs[kk][64 + tx * 4];
            #pragma unroll
            for (int i = 0; i < 8; i++)
                #pragma unroll
                for (int j = 0; j < 8; j++)
                    acc[i][j] = fmaf(ar[i], br[j], acc[i][j]);
        }
        __syncthreads();
    }

    #pragma unroll
    for (int ih = 0; ih < 2; ih++) {
        #pragma unroll
        for (int i = 0; i < 4; i++) {
            const int row = brow + ih * 64 + ty * 4 + i;
            #pragma unroll
            for (int jh = 0; jh < 2; jh++) {
                const int col = bcol + jh * 64 + tx * 4;
                float4 o;
                o.x = acc[ih * 4 + i][jh * 4 + 0] + bias[col + 0];
                o.y = acc[ih * 4 + i][jh * 4 + 1] + bias[col + 1];
                o.z = acc[ih * 4 + i][jh * 4 + 2] + bias[col + 2];
                o.w = acc[ih * 4 + i][jh * 4 + 3] + bias[col + 3];
                *(float4*)&C[(size_t)row * N + col] = o;
            }
        }
    }
}

// ---------------------------------------------------------------------------
// Causal flash attention (fp32). Grid: (qb=32, h=16, b=2). Block: 256 thr.
// Br=Bc=64. 16x16 threads, 4x4 register tile each for S and O.
// Q,K stored d-major (transposed) in smem for float4 reads; V row-major.
// ---------------------------------------------------------------------------
#define PADQ 68   // row stride for transposed tiles (272B: 16B-aligned, spreads banks)

__global__ __launch_bounds__(256) void attn_kernel()
{
    extern __shared__ float sm[];
    float* QsT = sm;                       // [64][PADQ]  QsT[d][r]
    float* KsT = QsT + 64 * PADQ;          // [64][PADQ]  KsT[d][c]
    float* Vs  = KsT + 64 * PADQ;          // [64][64]    Vs[kk][d]
    float* Ps  = Vs + 64 * 64;             // [64][64]    Ps[r][kk]

    const int qb = blockIdx.x;
    const int h  = blockIdx.y;
    const int b  = blockIdx.z;
    const int tid = threadIdx.x;
    const int tx = tid & 15;
    const int ty = tid >> 4;
    const int qbase = qb * 64;
    const size_t base = (size_t)b * SEQ * DMODEL + (size_t)h * HDIM;

    // Load Q tile, transposed + pre-scaled by 1/sqrt(Hd)
    #pragma unroll
    for (int it = 0; it < 4; it++) {
        int f   = tid + 256 * it;       // float4 index within 64x64 tile
        int row = f >> 4;
        int cg  = (f & 15) << 2;
        float4 v = *(const float4*)&g_Q[base + (size_t)(qbase + row) * DMODEL + cg];
        QsT[(cg + 0) * PADQ + row] = v.x * 0.125f;
        QsT[(cg + 1) * PADQ + row] = v.y * 0.125f;
        QsT[(cg + 2) * PADQ + row] = v.z * 0.125f;
        QsT[(cg + 3) * PADQ + row] = v.w * 0.125f;
    }

    float o[4][4];
    float m[4], l[4];
    #pragma unroll
    for (int i = 0; i < 4; i++) {
        m[i] = -1e30f; l[i] = 0.f;
        #pragma unroll
        for (int j = 0; j < 4; j++) o[i][j] = 0.f;
    }

    for (int kb = 0; kb <= qb; kb++) {
        __syncthreads();   // previous iter's Ps/Vs consumed; QsT ready on iter 0
        const int kbase = kb * 64;

        #pragma unroll
        for (int it = 0; it < 4; it++) {
            int f   = tid + 256 * it;
            int row = f >> 4;
            int cg  = (f & 15) << 2;
            const size_t goff = base + (size_t)(kbase + row) * DMODEL + cg;
            float4 kv = *(const float4*)&g_K[goff];
            KsT[(cg + 0) * PADQ + row] = kv.x;
            KsT[(cg + 1) * PADQ + row] = kv.y;
            KsT[(cg + 2) * PADQ + row] = kv.z;
            KsT[(cg + 3) * PADQ + row] = kv.w;
            float4 vv = *(const float4*)&g_V[goff];
            *(float4*)&Vs[row * 64 + cg] = vv;
        }
        __syncthreads();

        // S = Q @ K^T (scaled)
        float s[4][4];
        #pragma unroll
        for (int i = 0; i < 4; i++)
            #pragma unroll
            for (int j = 0; j < 4; j++) s[i][j] = 0.f;

        #pragma unroll 8
        for (int d = 0; d < 64; d++) {
            float qa[4], ka[4];
            *(float4*)qa = *(const float4*)&QsT[d * PADQ + ty * 4];
            *(float4*)ka = *(const float4*)&KsT[d * PADQ + tx * 4];
            #pragma unroll
            for (int i = 0; i < 4; i++)
                #pragma unroll
                for (int j = 0; j < 4; j++)
                    s[i][j] = fmaf(qa[i], ka[j], s[i][j]);
        }

        // Online softmax (per q row; 16 threads per row group compute
        // identical stats via butterfly shuffles within 16-lane halves)
        const bool diag = (kb == qb);
        #pragma unroll
        for (int i = 0; i < 4; i++) {
            const int r = ty * 4 + i;
            float rm = -1e30f;
            #pragma unroll
            for (int j = 0; j < 4; j++) {
                if (diag && (tx * 4 + j) > r) s[i][j] = -1e30f;
                rm = fmaxf(rm, s[i][j]);
            }
            rm = fmaxf(rm, __shfl_xor_sync(0xffffffffu, rm, 1));
            rm = fmaxf(rm, __shfl_xor_sync(0xffffffffu, rm, 2));
            rm = fmaxf(rm, __shfl_xor_sync(0xffffffffu, rm, 4));
            rm = fmaxf(rm, __shfl_xor_sync(0xffffffffu, rm, 8));
            const float mnew = fmaxf(m[i], rm);
            const float corr = __expf(m[i] - mnew);
            float pv[4];
            float rs = 0.f;
            #pragma unroll
            for (int j = 0; j < 4; j++) {
                float p = __expf(s[i][j] - mnew);
                pv[j] = p;
                rs += p;
            }
            *(float4*)&Ps[r * 64 + tx * 4] = make_float4(pv[0], pv[1], pv[2], pv[3]);
            rs += __shfl_xor_sync(0xffffffffu, rs, 1);
            rs += __shfl_xor_sync(0xffffffffu, rs, 2);
            rs += __shfl_xor_sync(0xffffffffu, rs, 4);
            rs += __shfl_xor_sync(0xffffffffu, rs, 8);
            l[i] = l[i] * corr + rs;
            m[i] = mnew;
            #pragma unroll
            for (int j = 0; j < 4; j++) o[i][j] *= corr;
        }
        __syncthreads();

        // O += P @ V
        #pragma unroll 4
        for (int kk = 0; kk < 64; kk++) {
            float va[4];
            *(float4*)va = *(const float4*)&Vs[kk * 64 + tx * 4];
            #pragma unroll
            for (int i = 0; i < 4; i++) {
                const float p = Ps[(ty * 4 + i) * 64 + kk];
                #pragma unroll
                for (int j = 0; j < 4; j++)
                    o[i][j] = fmaf(p, va[j], o[i][j]);
            }
        }
    }

    // Normalize and write attention output (layout [B,S,H*Hd])
    #pragma unroll
    for (int i = 0; i < 4; i++) {
        const int r = qbase + ty * 4 + i;
        const float inv = 1.0f / l[i];
        float4 ov = make_float4(o[i][0] * inv, o[i][1] * inv,
                                o[i][2] * inv, o[i][3] * inv);
        *(float4*)&g_AO[base + (size_t)r * DMODEL + tx * 4] = ov;
    }
}

// ---------------------------------------------------------------------------
// Launch
// ---------------------------------------------------------------------------
#define ATTN_SMEM ((64 * PADQ * 2 + 64 * 64 * 2) * sizeof(float))  // 67584 B

extern "C" void kernel_launch(void* const* d_in, const int* in_sizes, int n_in,
                              void* d_out, int out_size)
{
    const float* X  = (const float*)d_in[0];
    const float* Wq = (const float*)d_in[1];
    const float* bq = (const float*)d_in[2];
    const float* Wk = (const float*)d_in[3];
    const float* bk = (const float*)d_in[4];
    const float* Wv = (const float*)d_in[5];
    const float* bv = (const float*)d_in[6];
    const float* Wo = (const float*)d_in[7];
    const float* bo = (const float*)d_in[8];
    float* out = (float*)d_out;

    float *Qp, *Kp, *Vp, *AOp;
    cudaGetSymbolAddress((void**)&Qp,  g_Q);
    cudaGetSymbolAddress((void**)&Kp,  g_K);
    cudaGetSymbolAddress((void**)&Vp,  g_V);
    cudaGetSymbolAddress((void**)&AOp, g_AO);

    cudaFuncSetAttribute(attn_kernel,
                         cudaFuncAttributeMaxDynamicSharedMemorySize,
                         (int)ATTN_SMEM);

    dim3 gg(DMODEL / 128, MROWS / 128);   // (8, 32)
    dim3 gt(256);

    sgemm_bias<<<gg, gt>>>(X, Wq, bq, Qp, MROWS, DMODEL, DMODEL);
    sgemm_bias<<<gg, gt>>>(X, Wk, bk, Kp, MROWS, DMODEL, DMODEL);
    sgemm_bias<<<gg, gt>>>(X, Wv, bv, Vp, MROWS, DMODEL, DMODEL);

    attn_kernel<<<dim3(SEQ / 64, NHEADS, BATCH), 256, ATTN_SMEM>>>();

    sgemm_bias<<<gg, gt>>>(AOp, Wo, bo, out, MROWS, DMODEL, DMODEL);
}

// round 3
// speedup vs baseline: 2.5015x; 2.5015x over previous
#include <cuda_runtime.h>
#include <cuda_bf16.h>
#include <math.h>
#include <stdint.h>

#define BATCH 2
#define SEQ   2048
#define DM    1024
#define NH    16
#define HD    64
#define MR    (BATCH*SEQ)   // 4096

// ---------------------------------------------------------------------------
// Scratch (allocation-free rule: device globals)
// ---------------------------------------------------------------------------
__device__ __nv_bfloat16 g_Xhi[(size_t)MR * DM];
__device__ __nv_bfloat16 g_Xlo[(size_t)MR * DM];
// WT rows: 0-1023 WqT, 1024-2047 WkT, 2048-3071 WvT, 3072-4095 WoT  ([n][k])
__device__ __nv_bfloat16 g_WThi[(size_t)4096 * DM];
__device__ __nv_bfloat16 g_WTlo[(size_t)4096 * DM];
__device__ float         g_bias[4096];          // bq|bk|bv|bo
__device__ __nv_bfloat16 g_QKVhi[(size_t)MR * 3072];
__device__ __nv_bfloat16 g_QKVlo[(size_t)MR * 3072];
__device__ __nv_bfloat16 g_AOhi[(size_t)MR * DM];
__device__ __nv_bfloat16 g_AOlo[(size_t)MR * DM];

// ---------------------------------------------------------------------------
// PTX helpers (all sm_80-era: compile at compute_103)
// ---------------------------------------------------------------------------
__device__ __forceinline__ uint32_t smem_u32(const void* p) {
    uint32_t a;
    asm("{ .reg .u64 t; cvta.to.shared.u64 t, %1; cvt.u32.u64 %0, t; }"
        : "=r"(a) : "l"(p));
    return a;
}

__device__ __forceinline__ void mma_bf16(float* d, const uint32_t* a, const uint32_t* b) {
    asm volatile(
        "mma.sync.aligned.m16n8k16.row.col.f32.bf16.bf16.f32 "
        "{%0,%1,%2,%3}, {%4,%5,%6,%7}, {%8,%9}, {%0,%1,%2,%3};"
        : "+f"(d[0]), "+f"(d[1]), "+f"(d[2]), "+f"(d[3])
        : "r"(a[0]), "r"(a[1]), "r"(a[2]), "r"(a[3]), "r"(b[0]), "r"(b[1]));
}

__device__ __forceinline__ void ldm_x4(uint32_t* r, uint32_t addr) {
    asm volatile("ldmatrix.sync.aligned.m8n8.x4.shared.b16 {%0,%1,%2,%3}, [%4];"
                 : "=r"(r[0]), "=r"(r[1]), "=r"(r[2]), "=r"(r[3]) : "r"(addr));
}
__device__ __forceinline__ void ldm_x2t(uint32_t* r, uint32_t addr) {
    asm volatile("ldmatrix.sync.aligned.m8n8.x2.trans.shared.b16 {%0,%1}, [%2];"
                 : "=r"(r[0]), "=r"(r[1]) : "r"(addr));
}

#define CP16(sm, g) \
    asm volatile("cp.async.cg.shared.global [%0], [%1], 16;" :: "r"(sm), "l"(g))
#define CP_COMMIT asm volatile("cp.async.commit_group;")
#define CP_WAIT0  asm volatile("cp.async.wait_group 0;" ::: "memory")

__device__ __forceinline__ void split2(float a, float b, uint32_t& hi, uint32_t& lo) {
    __nv_bfloat162 H = __floats2bfloat162_rn(a, b);   // .x = a (low 16 bits)
    float ra = a - __bfloat162float(H.x);
    float rb = b - __bfloat162float(H.y);
    __nv_bfloat162 L = __floats2bfloat162_rn(ra, rb);
    hi = *(uint32_t*)&H;
    lo = *(uint32_t*)&L;
}

__device__ __forceinline__ void store_split(__nv_bfloat16* Chi, __nv_bfloat16* Clo,
                                            size_t idx, float v0, float v1) {
    uint32_t h, l;
    split2(v0, v1, h, l);
    *(uint32_t*)(Chi + idx) = h;
    *(uint32_t*)(Clo + idx) = l;
}

// ---------------------------------------------------------------------------
// Conversion kernels
// ---------------------------------------------------------------------------
__global__ void split_f32(const float* __restrict__ src,
                          __nv_bfloat16* __restrict__ hi,
                          __nv_bfloat16* __restrict__ lo, int n4)
{
    int i = blockIdx.x * blockDim.x + threadIdx.x;
    if (i >= n4) return;
    float4 v = ((const float4*)src)[i];
    store_split(hi, lo, 4 * (size_t)i,     v.x, v.y);
    store_split(hi, lo, 4 * (size_t)i + 2, v.z, v.w);
}

// W [K][N] fp32 -> WT hi/lo [N][K] bf16 (transpose + split)
__global__ void split_wT(const float* __restrict__ W,
                         __nv_bfloat16* __restrict__ Thi,
                         __nv_bfloat16* __restrict__ Tlo)
{
    __shared__ float t[32][33];
    const int k0 = blockIdx.y * 32, n0 = blockIdx.x * 32;
    const int tx = threadIdx.x, ty = threadIdx.y;
    #pragma unroll
    for (int i = ty; i < 32; i += 8)
        t[i][tx] = W[(size_t)(k0 + i) * DM + n0 + tx];
    __syncthreads();
    #pragma unroll
    for (int i = ty; i < 32; i += 8) {
        float v = t[tx][i];   // = W[k0+tx][n0+i]
        __nv_bfloat16 h = __float2bfloat16_rn(v);
        Thi[(size_t)(n0 + i) * DM + k0 + tx] = h;
        Tlo[(size_t)(n0 + i) * DM + k0 + tx] =
            __float2bfloat16_rn(v - __bfloat162float(h));
    }
}

__global__ void concat_bias(const float* bq, const float* bk, const float* bv,
                            const float* bo, float* dst)
{
    int i = blockIdx.x * blockDim.x + threadIdx.x;
    if (i >= 4096) return;
    float v;
    if      (i < 1024) v = bq[i];
    else if (i < 2048) v = bk[i - 1024];
    else if (i < 3072) v = bv[i - 2048];
    else               v = bo[i - 3072];
    dst[i] = v;
}

// ---------------------------------------------------------------------------
// Split-bf16 x3 GEMM on mma.sync:  C[M,N] = A[M,1024] @ B^T + bias
// A: Ahi/Alo [M][1024];  B: WT rows [N][1024]
// CTA 128x128, BK=32, 8 warps (4x2, warp tile 32x64), cp.async double buffer
// ---------------------------------------------------------------------------
#define TSZ 10240u   // one 128x40-b16 tile in bytes
#define GEMM_SMEM (8u * TSZ)   // 81920

template<bool TOF32>
__global__ __launch_bounds__(256) void gemm_mma(
    const __nv_bfloat16* __restrict__ Ahi, const __nv_bfloat16* __restrict__ Alo,
    const __nv_bfloat16* __restrict__ Bhi, const __nv_bfloat16* __restrict__ Blo,
    const float* __restrict__ bias, float* __restrict__ Cf,
    __nv_bfloat16* __restrict__ Chi, __nv_bfloat16* __restrict__ Clo,
    int ldc, int qscale)
{
    extern __shared__ char smc[];
    const uint32_t sb = smem_u32(smc);
    const int tid = threadIdx.x, lane = tid & 31, wid = tid >> 5;
    const int wm = wid >> 1, wn = wid & 1;
    const int g = lane >> 2, tg = lane & 3;
    const int brow = blockIdx.y * 128, bcol = blockIdx.x * 128;
    const int lr = tid >> 2, lq = tid & 3;   // load slot: row, quad

    auto issue = [&](int buf, int kc) {
        #pragma unroll
        for (int rep = 0; rep < 2; rep++) {
            int row = lr + rep * 64;
            size_t ga = (size_t)(brow + row) * DM + kc + lq * 8;
            size_t gb = (size_t)(bcol + row) * DM + kc + lq * 8;
            uint32_t off = sb + (uint32_t)buf * 4u * TSZ
                         + (uint32_t)(row * 40 + lq * 8) * 2u;
            CP16(off,            Ahi + ga);
            CP16(off + TSZ,      Alo + ga);
            CP16(off + 2u * TSZ, Bhi + gb);
            CP16(off + 3u * TSZ, Blo + gb);
        }
        CP_COMMIT;
    };

    float acc[2][8][4];
    #pragma unroll
    for (int a = 0; a < 2; a++)
        #pragma unroll
        for (int b = 0; b < 8; b++)
            #pragma unroll
            for (int c = 0; c < 4; c++) acc[a][b][c] = 0.f;

    issue(0, 0);

    for (int c = 0; c < 32; c++) {
        CP_WAIT0;
        __syncthreads();
        if (c < 31) issue((c + 1) & 1, (c + 1) * 32);
        const uint32_t tb = sb + (uint32_t)(c & 1) * 4u * TSZ;

        #pragma unroll
        for (int kk = 0; kk < 32; kk += 16) {
            uint32_t ah[2][4], al[2][4], bh[8][2], bl[8][2];
            #pragma unroll
            for (int fm = 0; fm < 2; fm++) {
                uint32_t ra = (uint32_t)((wm * 32 + fm * 16 + (lane & 7)
                              + 8 * ((lane >> 3) & 1)) * 40
                              + kk + 8 * (lane >> 4)) * 2u;
                ldm_x4(ah[fm], tb + ra);
                ldm_x4(al[fm], tb + TSZ + ra);
            }
            #pragma unroll
            for (int i = 0; i < 4; i++) {
                uint32_t rb = (uint32_t)((wn * 64 + i * 16 + (lane & 7)
                              + 8 * (lane >> 4)) * 40
                              + kk + 8 * ((lane >> 3) & 1)) * 2u;
                uint32_t t4[4];
                ldm_x4(t4, tb + 2u * TSZ + rb);
                bh[2*i][0] = t4[0]; bh[2*i][1] = t4[1];
                bh[2*i+1][0] = t4[2]; bh[2*i+1][1] = t4[3];
                ldm_x4(t4, tb + 3u * TSZ + rb);
                bl[2*i][0] = t4[0]; bl[2*i][1] = t4[1];
                bl[2*i+1][0] = t4[2]; bl[2*i+1][1] = t4[3];
            }
            #pragma unroll
            for (int fm = 0; fm < 2; fm++)
                #pragma unroll
                for (int fn = 0; fn < 8; fn++) {
                    mma_bf16(acc[fm][fn], ah[fm], bh[fn]);
                    mma_bf16(acc[fm][fn], ah[fm], bl[fn]);
                    mma_bf16(acc[fm][fn], al[fm], bh[fn]);
                }
        }
    }

    // epilogue
    #pragma unroll
    for (int fm = 0; fm < 2; fm++) {
        int row = brow + wm * 32 + fm * 16 + g;
        #pragma unroll
        for (int fn = 0; fn < 8; fn++) {
            int col = bcol + wn * 64 + fn * 8 + 2 * tg;
            float sc = (qscale && col < 1024) ? 0.125f : 1.0f;
            float b0 = bias[col], b1 = bias[col + 1];
            float v0 = (acc[fm][fn][0] + b0) * sc;
            float v1 = (acc[fm][fn][1] + b1) * sc;
            float v2 = (acc[fm][fn][2] + b0) * sc;
            float v3 = (acc[fm][fn][3] + b1) * sc;
            if (TOF32) {
                *(float2*)&Cf[(size_t)row * ldc + col]       = make_float2(v0, v1);
                *(float2*)&Cf[(size_t)(row + 8) * ldc + col] = make_float2(v2, v3);
            } else {
                store_split(Chi, Clo, (size_t)row * ldc + col,       v0, v1);
                store_split(Chi, Clo, (size_t)(row + 8) * ldc + col, v2, v3);
            }
        }
    }
}

// ---------------------------------------------------------------------------
// Flash attention on mma.sync, split-bf16 x3 for S=QK^T and O=PV.
// Grid (32 qtiles, 16 h, 2 b), 128 threads (4 warps, m16 each), Bc=64.
// Q pre-scaled by 1/8 at the QKV GEMM epilogue.
// ---------------------------------------------------------------------------
#define AST 72        // b16 row stride (144B: 16B-aligned, ldmatrix conflict-free)
#define QHI_O 0u
#define QLO_O 9216u
#define KHI_O 18432u
#define KLO_O 27648u
#define VHI_O 36864u
#define VLO_O 46080u
#define ATTN_SMEM 55296

__global__ __launch_bounds__(128) void attn_mma()
{
    extern __shared__ char smc[];
    const uint32_t sb = smem_u32(smc);
    const int tid = threadIdx.x, lane = tid & 31, w = tid >> 5;
    const int g = lane >> 2, tg = lane & 3;
    const int qb = blockIdx.x, h = blockIdx.y, b = blockIdx.z;
    const int qbase = qb * 64;
    const size_t rowb = (size_t)b * SEQ;
    const int hoff = h * HD;

    // load Q tile (hi/lo), 64 rows x 64 bf16
    #pragma unroll
    for (int i = 0; i < 4; i++) {
        int slot = tid + 128 * i;
        int r = slot >> 3, q8 = slot & 7;
        size_t go = (rowb + qbase + r) * 3072 + hoff + q8 * 8;
        uint32_t so = (uint32_t)(r * AST + q8 * 8) * 2u;
        *(uint4*)(smc + QHI_O + so) = *(const uint4*)(g_QKVhi + go);
        *(uint4*)(smc + QLO_O + so) = *(const uint4*)(g_QKVlo + go);
    }

    float o[8][4];
    #pragma unroll
    for (int fn = 0; fn < 8; fn++)
        #pragma unroll
        for (int c = 0; c < 4; c++) o[fn][c] = 0.f;
    float m0 = -1e30f, m1 = -1e30f, l0 = 0.f, l1 = 0.f;

    for (int kb = 0; kb <= qb; kb++) {
        __syncthreads();   // Q visible (first) / prev compute done (later)
        const int kbase = kb * 64;
        #pragma unroll
        for (int i = 0; i < 4; i++) {
            int slot = tid + 128 * i;
            int r = slot >> 3, q8 = slot & 7;
            size_t go = (rowb + kbase + r) * 3072 + hoff + q8 * 8;
            uint32_t so = (uint32_t)(r * AST + q8 * 8) * 2u;
            *(uint4*)(smc + KHI_O + so) = *(const uint4*)(g_QKVhi + go + 1024);
            *(uint4*)(smc + KLO_O + so) = *(const uint4*)(g_QKVlo + go + 1024);
            *(uint4*)(smc + VHI_O + so) = *(const uint4*)(g_QKVhi + go + 2048);
            *(uint4*)(smc + VLO_O + so) = *(const uint4*)(g_QKVlo + go + 2048);
        }
        __syncthreads();

        // ---- S = Q @ K^T ----
        float s[8][4];
        #pragma unroll
        for (int fn = 0; fn < 8; fn++)
            #pragma unroll
            for (int c = 0; c < 4; c++) s[fn][c] = 0.f;

        #pragma unroll
        for (int kk = 0; kk < 64; kk += 16) {
            uint32_t qh[4], ql[4];
            uint32_t ra = sb + (uint32_t)((w * 16 + (lane & 7)
                          + 8 * ((lane >> 3) & 1)) * AST
                          + kk + 8 * (lane >> 4)) * 2u;
            ldm_x4(qh, ra + QHI_O);
            ldm_x4(ql, ra + QLO_O);
            uint32_t kh[8][2], kl[8][2];
            #pragma unroll
            for (int i = 0; i < 4; i++) {
                uint32_t rb = sb + (uint32_t)((i * 16 + (lane & 7)
                              + 8 * (lane >> 4)) * AST
                              + kk + 8 * ((lane >> 3) & 1)) * 2u;
                uint32_t t4[4];
                ldm_x4(t4, rb + KHI_O);
                kh[2*i][0] = t4[0]; kh[2*i][1] = t4[1];
                kh[2*i+1][0] = t4[2]; kh[2*i+1][1] = t4[3];
                ldm_x4(t4, rb + KLO_O);
                kl[2*i][0] = t4[0]; kl[2*i][1] = t4[1];
                kl[2*i+1][0] = t4[2]; kl[2*i+1][1] = t4[3];
            }
            #pragma unroll
            for (int fn = 0; fn < 8; fn++) {
                mma_bf16(s[fn], qh, kh[fn]);
                mma_bf16(s[fn], qh, kl[fn]);
                mma_bf16(s[fn], ql, kh[fn]);
            }
        }

        // ---- causal mask on diagonal tile ----
        if (kb == qb) {
            const int lr0 = w * 16 + g, lr1 = lr0 + 8;
            #pragma unroll
            for (int fn = 0; fn < 8; fn++) {
                int c0 = fn * 8 + 2 * tg;
                if (c0     > lr0) s[fn][0] = -1e30f;
                if (c0 + 1 > lr0) s[fn][1] = -1e30f;
                if (c0     > lr1) s[fn][2] = -1e30f;
                if (c0 + 1 > lr1) s[fn][3] = -1e30f;
            }
        }

        // ---- online softmax (rows g and g+8 of this warp's 16) ----
        float rm0 = -1e30f, rm1 = -1e30f;
        #pragma unroll
        for (int fn = 0; fn < 8; fn++) {
            rm0 = fmaxf(rm0, fmaxf(s[fn][0], s[fn][1]));
            rm1 = fmaxf(rm1, fmaxf(s[fn][2], s[fn][3]));
        }
        rm0 = fmaxf(rm0, __shfl_xor_sync(0xffffffffu, rm0, 1));
        rm0 = fmaxf(rm0, __shfl_xor_sync(0xffffffffu, rm0, 2));
        rm1 = fmaxf(rm1, __shfl_xor_sync(0xffffffffu, rm1, 1));
        rm1 = fmaxf(rm1, __shfl_xor_sync(0xffffffffu, rm1, 2));
        const float mn0 = fmaxf(m0, rm0), mn1 = fmaxf(m1, rm1);
        const float c0 = __expf(m0 - mn0), c1 = __expf(m1 - mn1);
        m0 = mn0; m1 = mn1;
        float sum0 = 0.f, sum1 = 0.f;
        #pragma unroll
        for (int fn = 0; fn < 8; fn++) {
            s[fn][0] = __expf(s[fn][0] - mn0); sum0 += s[fn][0];
            s[fn][1] = __expf(s[fn][1] - mn0); sum0 += s[fn][1];
            s[fn][2] = __expf(s[fn][2] - mn1); sum1 += s[fn][2];
            s[fn][3] = __expf(s[fn][3] - mn1); sum1 += s[fn][3];
        }
        sum0 += __shfl_xor_sync(0xffffffffu, sum0, 1);
        sum0 += __shfl_xor_sync(0xffffffffu, sum0, 2);
        sum1 += __shfl_xor_sync(0xffffffffu, sum1, 1);
        sum1 += __shfl_xor_sync(0xffffffffu, sum1, 2);
        l0 = l0 * c0 + sum0;
        l1 = l1 * c1 + sum1;
        #pragma unroll
        for (int fn = 0; fn < 8; fn++) {
            o[fn][0] *= c0; o[fn][1] *= c0;
            o[fn][2] *= c1; o[fn][3] *= c1;
        }

        // ---- O += P @ V  (P from S regs; V via ldmatrix.trans) ----
        #pragma unroll
        for (int kk = 0; kk < 64; kk += 16) {
            const int f0 = kk >> 3, f1 = f0 + 1;
            uint32_t ph[4], pl[4];
            split2(s[f0][0], s[f0][1], ph[0], pl[0]);
            split2(s[f0][2], s[f0][3], ph[1], pl[1]);
            split2(s[f1][0], s[f1][1], ph[2], pl[2]);
            split2(s[f1][2], s[f1][3], ph[3], pl[3]);
            uint32_t rv = sb + (uint32_t)((kk + (lane & 15)) * AST) * 2u;
            #pragma unroll
            for (int fn = 0; fn < 8; fn++) {
                uint32_t vh[2], vl[2];
                ldm_x2t(vh, rv + VHI_O + (uint32_t)(fn * 16));
                ldm_x2t(vl, rv + VLO_O + (uint32_t)(fn * 16));
                mma_bf16(o[fn], ph, vh);
                mma_bf16(o[fn], ph, vl);
                mma_bf16(o[fn], pl, vh);
            }
        }
    }

    // ---- epilogue: normalize, split-store AO ----
    const float i0 = 1.f / l0, i1 = 1.f / l1;
    const size_t r0 = rowb + qbase + w * 16 + g;
    #pragma unroll
    for (int fn = 0; fn < 8; fn++) {
        int col = hoff + fn * 8 + 2 * tg;
        store_split(g_AOhi, g_AOlo, r0 * DM + col,       o[fn][0] * i0, o[fn][1] * i0);
        store_split(g_AOhi, g_AOlo, (r0 + 8) * DM + col, o[fn][2] * i1, o[fn][3] * i1);
    }
}

// ---------------------------------------------------------------------------
// Launch
// ---------------------------------------------------------------------------
extern "C" void kernel_launch(void* const* d_in, const int* in_sizes, int n_in,
                              void* d_out, int out_size)
{
    const float* X  = (const float*)d_in[0];
    const float* Wq = (const float*)d_in[1];
    const float* bq = (const float*)d_in[2];
    const float* Wk = (const float*)d_in[3];
    const float* bk = (const float*)d_in[4];
    const float* Wv = (const float*)d_in[5];
    const float* bv = (const float*)d_in[6];
    const float* Wo = (const float*)d_in[7];
    const float* bo = (const float*)d_in[8];
    float* out = (float*)d_out;

    __nv_bfloat16 *Xhi, *Xlo, *WThi, *WTlo, *QKVhi, *QKVlo, *AOhi, *AOlo;
    float* biasP;
    cudaGetSymbolAddress((void**)&Xhi,   g_Xhi);
    cudaGetSymbolAddress((void**)&Xlo,   g_Xlo);
    cudaGetSymbolAddress((void**)&WThi,  g_WThi);
    cudaGetSymbolAddress((void**)&WTlo,  g_WTlo);
    cudaGetSymbolAddress((void**)&QKVhi, g_QKVhi);
    cudaGetSymbolAddress((void**)&QKVlo, g_QKVlo);
    cudaGetSymbolAddress((void**)&AOhi,  g_AOhi);
    cudaGetSymbolAddress((void**)&AOlo,  g_AOlo);
    cudaGetSymbolAddress((void**)&biasP, g_bias);

    cudaFuncSetAttribute(gemm_mma<false>,
        cudaFuncAttributeMaxDynamicSharedMemorySize, (int)GEMM_SMEM);
    cudaFuncSetAttribute(gemm_mma<true>,
        cudaFuncAttributeMaxDynamicSharedMemorySize, (int)GEMM_SMEM);
    cudaFuncSetAttribute(attn_mma,
        cudaFuncAttributeMaxDynamicSharedMemorySize, (int)ATTN_SMEM);

    const size_t WSZ = (size_t)DM * DM;
    const int n4 = MR * DM / 4;
    dim3 tgrid(DM / 32, DM / 32);
    dim3 tblk(32, 8);

    split_f32<<<(n4 + 255) / 256, 256>>>(X, Xhi, Xlo, n4);
    split_wT<<<tgrid, tblk>>>(Wq, WThi + 0 * WSZ, WTlo + 0 * WSZ);
    split_wT<<<tgrid, tblk>>>(Wk, WThi + 1 * WSZ, WTlo + 1 * WSZ);
    split_wT<<<tgrid, tblk>>>(Wv, WThi + 2 * WSZ, WTlo + 2 * WSZ);
    split_wT<<<tgrid, tblk>>>(Wo, WThi + 3 * WSZ, WTlo + 3 * WSZ);
    concat_bias<<<16, 256>>>(bq, bk, bv, bo, biasP);

    // fused QKV projection (N=3072), Q region scaled by 1/8, split-bf16 out
    gemm_mma<false><<<dim3(24, 32), 256, GEMM_SMEM>>>(
        Xhi, Xlo, WThi, WTlo, biasP, nullptr, QKVhi, QKVlo, 3072, 1);

    // causal attention, split-bf16 out
    attn_mma<<<dim3(SEQ / 64, NH, BATCH), 128, ATTN_SMEM>>>();

    // output projection, fp32 out
    gemm_mma<true><<<dim3(8, 32), 256, GEMM_SMEM>>>(
        AOhi, AOlo, WThi + 3 * WSZ, WTlo + 3 * WSZ, biasP + 3072,
        out, nullptr, nullptr, 1024, 0);
}